// round 11
// baseline (speedup 1.0000x reference)
#include <cuda_runtime.h>

// ContrastiveTreeLoss — final form: delta formulation, one warp per sentence,
// 512 single-warp CTAs, single launch, no __syncthreads, no smem.
//
// Shapes (fixed by the problem instance):
//   arc_scores [B=512, N=256, N=256] f32
//   gold_heads [B, N] i32
//   mask       [B, N] i32
//   neg_heads  [K=4, B, N] i32
//   out        scalar f32 = mean_{k,b} relu(MARGIN - gold_total[b] + neg_total[k,b])
//
// Delta identity: each negative tree is gold with <=2 changed heads, so
//   margin - gold_total + neg_total_k
//     = margin + sum_{d: nh!=gh} mask[d] * (arc[b,nh,d] - arc[b,gh,d])
// i.e. the 130K-point random gather of the naive formulation reduces to ~8K
// scattered loads chip-wide plus ~3MB of perfectly coalesced index streams.
//
// Session finding (R5/R7/R9/R10): wall time is pinned at the harness graph-
// replay floor (~8.67us) for every kernel whose true runtime is below ~8us.
// This version minimizes true kernel runtime (~2us critical path: one round of
// 12 coalesced int4 index loads issued back-to-back, one dependent round of
// rare predicated scattered loads, warp reduce, arrive) and carries the least
// machinery: no shared memory, no block barriers, single-warp CTAs.

#define TL_B 512
#define TL_N 256
#define TL_K 4
#define TL_MARGIN 2.0f

__device__ float g_partial[TL_B];
__device__ unsigned int g_done_count;   // zero-init; reset each launch by last CTA

__global__ __launch_bounds__(32)
void tree_loss_v6_kernel(const float* __restrict__ arc,
                         const int*   __restrict__ gold,
                         const int*   __restrict__ mask,
                         const int*   __restrict__ neg,
                         float*       __restrict__ out)
{
    const int lane = threadIdx.x;                 // 0..31
    const int b    = blockIdx.x;                  // sentence

    const float* __restrict__ arcb  = arc + (size_t)b * TL_N * TL_N;
    const int4*  __restrict__ gold4 = (const int4*)(gold + b * TL_N);
    const int4*  __restrict__ mask4 = (const int4*)(mask + b * TL_N);

    // ---- issue ALL coalesced index loads up front (12 x LDG.128, full MLP) ----
    int4 g4[2], m4[2], n4[2][TL_K];
#pragma unroll
    for (int i = 0; i < 2; i++) {
        const int idx = i * 32 + lane;            // int4 index within the row
        g4[i] = __ldg(gold4 + idx);
        m4[i] = __ldg(mask4 + idx);
#pragma unroll
        for (int k = 0; k < TL_K; k++) {
            const int4* __restrict__ neg4 =
                (const int4*)(neg + ((size_t)k * TL_B + b) * TL_N);
            n4[i][k] = __ldg(neg4 + idx);
        }
    }

    float dk[TL_K] = {0.0f, 0.0f, 0.0f, 0.0f};

#pragma unroll
    for (int i = 0; i < 2; i++) {
        const int d0 = (i * 32 + lane) * 4;       // first dependent of this int4
        const int   gh[4] = {g4[i].x, g4[i].y, g4[i].z, g4[i].w};
        const float mm[4] = {(float)m4[i].x, (float)m4[i].y,
                             (float)m4[i].z, (float)m4[i].w};
#pragma unroll
        for (int k = 0; k < TL_K; k++) {
            const int nh[4] = {n4[i][k].x, n4[i][k].y, n4[i][k].z, n4[i][k].w};
#pragma unroll
            for (int j = 0; j < 4; j++) {
                const int d = d0 + j;
                if (d >= 1) {                     // dependent 0 excluded
                    int g = min(max(gh[j], 0), TL_N - 1);
                    int n = min(max(nh[j], 0), TL_N - 1);
                    if (n != g) {
                        // Rare path: <=2 lanes per (k, sentence). Predicated
                        // scattered loads; no wavefronts on inactive lanes.
                        dk[k] += (__ldg(arcb + n * TL_N + d) -
                                  __ldg(arcb + g * TL_N + d)) * mm[j];
                    }
                }
            }
        }
    }

    // ---- warp reduction of the 4 deltas, then the per-sentence loss ----
#pragma unroll
    for (int k = 0; k < TL_K; k++) {
#pragma unroll
        for (int off = 16; off > 0; off >>= 1)
            dk[k] += __shfl_down_sync(0xffffffffu, dk[k], off);
    }

    unsigned int prev = 0xffffffffu;
    if (lane == 0) {
        float loss = 0.0f;
#pragma unroll
        for (int k = 0; k < TL_K; k++)
            loss += fmaxf(TL_MARGIN + dk[k], 0.0f);
        g_partial[b] = loss;
        __threadfence();                          // release partial before arrival
        prev = atomicAdd(&g_done_count, 1u);
    }
    // broadcast "am I the last CTA" to the whole warp
    const bool is_last =
        (__shfl_sync(0xffffffffu, prev, 0) == (unsigned int)(TL_B - 1));

    if (is_last) {
        __threadfence();                          // acquire all writers' partials
        // 32 lanes reduce 512 partials: 16 serial adds/lane then warp reduce.
        float v = 0.0f;
#pragma unroll
        for (int i = 0; i < TL_B / 32; i++)
            v += g_partial[i * 32 + lane];
#pragma unroll
        for (int off = 16; off > 0; off >>= 1)
            v += __shfl_down_sync(0xffffffffu, v, off);
        if (lane == 0) {
            out[0] = v * (1.0f / (float)(TL_K * TL_B));
            atomicExch(&g_done_count, 0u);        // reset for next graph replay
        }
    }
}

extern "C" void kernel_launch(void* const* d_in, const int* in_sizes, int n_in,
                              void* d_out, int out_size)
{
    const float* arc  = (const float*)d_in[0];  // arc_scores [B,N,N]
    const int*   gold = (const int*)  d_in[1];  // gold_heads [B,N]
    const int*   mask = (const int*)  d_in[2];  // mask       [B,N]
    const int*   neg  = (const int*)  d_in[3];  // neg_heads  [K,B,N]
    (void)in_sizes; (void)n_in; (void)out_size;

    tree_loss_v6_kernel<<<TL_B, 32>>>(arc, gold, mask, neg, (float*)d_out);
}